// round 16
// baseline (speedup 1.0000x reference)
#include <cuda_runtime.h>
#include <cuda_bf16.h>

#define BATCH 8
#define C 64
#define CK 8
#define L 4096
#define LT 64      // l per tile
#define MTILE 128  // m per block
#define NT (L / LT)

#define ROWB 144   // padded row: 64 bf16 = 128B + 16B pad (9 x 16B chunks, gcd(9,8)=1)

// dynamic smem layout (bytes)
#define EOFF 0                  // e: [buf2][ver2][128][ROWB] = 73728
#define EBUF 36864
#define EVER 18432
#define VOFF 73728              // v: [buf2][ver2][64][ROWB] = 36864
#define VBUF 18432
#define VVER 9216
#define DNOFF 110592            // denom [2][128] f32 = 1024
#define SMEM_BYTES 111616

__device__ float g_q[BATCH][L][CK];
__device__ float g_k[BATCH][L][CK];
__device__ __nv_bfloat16 g_vh[BATCH][C][L];
__device__ __nv_bfloat16 g_vl[BATCH][C][L];

__device__ __forceinline__ unsigned smem_u32(const void* p) {
    unsigned a;
    asm("{ .reg .u64 t; cvta.to.shared.u64 t, %1; cvt.u32.u64 %0, t; }" : "=r"(a) : "l"(p));
    return a;
}
__device__ __forceinline__ void ldm_x4(unsigned* r, unsigned addr) {
    asm volatile("ldmatrix.sync.aligned.m8n8.x4.shared.b16 {%0,%1,%2,%3}, [%4];"
        : "=r"(r[0]), "=r"(r[1]), "=r"(r[2]), "=r"(r[3]) : "r"(addr));
}
__device__ __forceinline__ void ldm_x2(unsigned* r, unsigned addr) {
    asm volatile("ldmatrix.sync.aligned.m8n8.x2.shared.b16 {%0,%1}, [%2];"
        : "=r"(r[0]), "=r"(r[1]) : "r"(addr));
}
__device__ __forceinline__ void mma16816(float* d, const unsigned* a, const unsigned* b) {
    asm volatile("mma.sync.aligned.m16n8k16.row.col.f32.bf16.bf16.f32 "
        "{%0,%1,%2,%3}, {%4,%5,%6,%7}, {%8,%9}, {%0,%1,%2,%3};"
        : "+f"(d[0]), "+f"(d[1]), "+f"(d[2]), "+f"(d[3])
        : "r"(a[0]), "r"(a[1]), "r"(a[2]), "r"(a[3]), "r"(b[0]), "r"(b[1]));
}
#define CP_ASYNC16(dst, src) \
    asm volatile("cp.async.cg.shared.global [%0], [%1], 16;" :: "r"(dst), "l"(src) : "memory")
#define CP_COMMIT()  asm volatile("cp.async.commit_group;" ::: "memory")
#define CP_WAIT0()   asm volatile("cp.async.wait_group 0;" ::: "memory")

// ============================================================
// Projection: q/k (f32) + v (bf16 hi/lo, transposed to [c][l])
// ============================================================
__global__ void __launch_bounds__(256) proj_kernel(
        const float* __restrict__ x,
        const float* __restrict__ Wq, const float* __restrict__ bq,
        const float* __restrict__ Wk, const float* __restrict__ bk,
        const float* __restrict__ Wv, const float* __restrict__ bv) {
    __shared__ float4 sWq[CK * 16], sWk[CK * 16], sWv[C * 16];
    __shared__ float sbq[CK], sbk[CK], sbv[C];
    __shared__ __align__(16) unsigned short s_t[C][256];
    int tid = threadIdx.x;
    for (int i = tid; i < CK * 16; i += 256) { sWq[i] = ((const float4*)Wq)[i]; sWk[i] = ((const float4*)Wk)[i]; }
    for (int i = tid; i < C * 16; i += 256) sWv[i] = ((const float4*)Wv)[i];
    if (tid < CK) { sbq[tid] = bq[tid]; sbk[tid] = bk[tid]; }
    if (tid < C) sbv[tid] = bv[tid];
    __syncthreads();

    int b = blockIdx.x;
    int l0 = blockIdx.y * 256;
    int l = l0 + tid;

    float xr[C];
#pragma unroll
    for (int c = 0; c < C; c++) xr[c] = x[((b * C) + c) * L + l];

    float outq[CK], outk[CK];
#pragma unroll
    for (int o = 0; o < CK; o++) {
        float aq = sbq[o], ak = sbk[o];
#pragma unroll
        for (int c4 = 0; c4 < 16; c4++) {
            float4 wq = sWq[o * 16 + c4];
            float4 wk = sWk[o * 16 + c4];
            aq += wq.x * xr[4*c4] + wq.y * xr[4*c4+1] + wq.z * xr[4*c4+2] + wq.w * xr[4*c4+3];
            ak += wk.x * xr[4*c4] + wk.y * xr[4*c4+1] + wk.z * xr[4*c4+2] + wk.w * xr[4*c4+3];
        }
        outq[o] = aq;
        outk[o] = ak;
    }
    *(float4*)&g_q[b][l][0] = make_float4(outq[0], outq[1], outq[2], outq[3]);
    *(float4*)&g_q[b][l][4] = make_float4(outq[4], outq[5], outq[6], outq[7]);
    *(float4*)&g_k[b][l][0] = make_float4(outk[0], outk[1], outk[2], outk[3]);
    *(float4*)&g_k[b][l][4] = make_float4(outk[4], outk[5], outk[6], outk[7]);

    float v[C];
#pragma unroll
    for (int og = 0; og < C; og += 4) {
        float a0 = sbv[og], a1 = sbv[og+1], a2 = sbv[og+2], a3 = sbv[og+3];
#pragma unroll
        for (int c4 = 0; c4 < 16; c4++) {
            float4 w0 = sWv[(og+0)*16 + c4];
            float4 w1 = sWv[(og+1)*16 + c4];
            float4 w2 = sWv[(og+2)*16 + c4];
            float4 w3 = sWv[(og+3)*16 + c4];
            float x0 = xr[4*c4], x1 = xr[4*c4+1], x2 = xr[4*c4+2], x3 = xr[4*c4+3];
            a0 += w0.x*x0 + w0.y*x1 + w0.z*x2 + w0.w*x3;
            a1 += w1.x*x0 + w1.y*x1 + w1.z*x2 + w1.w*x3;
            a2 += w2.x*x0 + w2.y*x1 + w2.z*x2 + w2.w*x3;
            a3 += w3.x*x0 + w3.y*x1 + w3.z*x2 + w3.w*x3;
        }
        v[og] = a0; v[og+1] = a1; v[og+2] = a2; v[og+3] = a3;
    }

    __syncthreads();
#pragma unroll
    for (int c = 0; c < C; c++)
        s_t[c][tid] = __bfloat16_as_ushort(__float2bfloat16(v[c]));
    __syncthreads();
    for (int idx = tid; idx < C * 32; idx += 256) {
        int c = idx >> 5, gr = idx & 31;
        *(uint4*)&g_vh[b][c][l0 + gr * 8] = *(const uint4*)&s_t[c][gr * 8];
    }
    __syncthreads();
#pragma unroll
    for (int c = 0; c < C; c++) {
        float hi = __bfloat162float(__float2bfloat16(v[c]));
        s_t[c][tid] = __bfloat16_as_ushort(__float2bfloat16(v[c] - hi));
    }
    __syncthreads();
    for (int idx = tid; idx < C * 32; idx += 256) {
        int c = idx >> 5, gr = idx & 31;
        *(uint4*)&g_vl[b][c][l0 + gr * 8] = *(const uint4*)&s_t[c][gr * 8];
    }
}

// ============================================================
// Attention. 256 threads (8 warps), MTILE=128, LT=64. Grid (8, 32).
// Pipelined: one __syncthreads per tile.
//   iter t: cp.async V(t+1) -> buf^ ; phase B(t) from buf ;
//           phase A(t+1) -> e in buf^ (q via __ldg) ; wait ; barrier.
// ============================================================
__global__ void __launch_bounds__(256)
attn_kernel(const float* __restrict__ x, const float* __restrict__ gamma_p,
            float* __restrict__ out) {
    extern __shared__ __align__(16) char sm[];
    float* denom_s = (float*)(sm + DNOFF);

    const int tid = threadIdx.x;
    const int lane = tid & 31;
    const int warp = tid >> 5;
    const int wm = warp >> 1;       // 0..3: m-group (32 m)
    const int wc = warp & 1;        // 0..1: c-group (32 c)
    const int b = blockIdx.x;
    const int m0 = blockIdx.y * MTILE;
    const int mA = tid & 127;       // phase-A m row
    const int half = tid >> 7;      // phase-A l half (32 l)

    const unsigned sb = smem_u32(sm);

    float4 k0 = *(const float4*)&g_k[b][m0 + mA][0];
    float4 k1 = *(const float4*)&g_k[b][m0 + mA][4];

    // ldmatrix lane-address components
    const unsigned e_base = (unsigned)(wm * 32 + (lane & 7)) * ROWB + ((lane >> 3) & 1) * 16u;
    const unsigned v_base = (unsigned)(wc * 32 + ((lane >> 3) & 1) * 8 + (lane & 7)) * ROWB
                          + ((lane >> 4) & 1) * 16u;

    float d[2][4][4];
#pragma unroll
    for (int i = 0; i < 2; i++)
#pragma unroll
        for (int nb = 0; nb < 4; nb++)
#pragma unroll
            for (int r = 0; r < 4; r++) d[i][nb][r] = 0.0f;
    float dsum = 0.0f;

    // ---------- phase A helper (computes tile tt into buffer bb) ----------
    auto phaseA = [&](int tt, int bb) {
        const int l0 = tt * LT;
#pragma unroll
        for (int lg = 0; lg < 4; lg++) {
            float e8[8];
#pragma unroll
            for (int li = 0; li < 8; li++) {
                int ll = half * 32 + lg * 8 + li;
                const float4* qp = (const float4*)&g_q[b][l0 + ll][0];
                float4 q0 = __ldg(qp);
                float4 q1 = __ldg(qp + 1);
                float s = q0.x*k0.x + q0.y*k0.y + q0.z*k0.z + q0.w*k0.w
                        + q1.x*k1.x + q1.y*k1.y + q1.z*k1.z + q1.w*k1.w;
                float e = __expf(s);
                dsum += e;
                e8[li] = e;
            }
            unsigned hw[4], lw[4];
#pragma unroll
            for (int p = 0; p < 4; p++) {
                __nv_bfloat162 hp = __floats2bfloat162_rn(e8[2*p], e8[2*p+1]);
                float h0 = __bfloat162float(hp.x), h1 = __bfloat162float(hp.y);
                __nv_bfloat162 lp = __floats2bfloat162_rn(e8[2*p] - h0, e8[2*p+1] - h1);
                hw[p] = *(unsigned*)&hp;
                lw[p] = *(unsigned*)&lp;
            }
            int lcol = half * 32 + lg * 8;
            char* ebase = sm + EOFF + bb * EBUF + mA * ROWB + lcol * 2;
            *(uint4*)(ebase)        = make_uint4(hw[0], hw[1], hw[2], hw[3]);
            *(uint4*)(ebase + EVER) = make_uint4(lw[0], lw[1], lw[2], lw[3]);
        }
    };

    // ---------- V staging via cp.async (tile tt into buffer bb) ----------
    auto stageV = [&](int tt, int bb) {
        const int l0 = tt * LT;
#pragma unroll
        for (int rep = 0; rep < 4; rep++) {
            int idx = tid + rep * 256;
            int ver = idx >> 9, rem = idx & 511;
            int c = rem >> 3, gr = rem & 7;
            const void* src = (const void*)((ver ? g_vl : g_vh)[b][c] + l0 + gr * 8);
            unsigned dst = sb + VOFF + bb * VBUF + ver * VVER + (unsigned)(c * ROWB + gr * 16);
            CP_ASYNC16(dst, src);
        }
        CP_COMMIT();
    };

    // prologue: tile 0 into buf 0
    stageV(0, 0);
    phaseA(0, 0);
    CP_WAIT0();
    __syncthreads();

    for (int t = 0; t < NT; t++) {
        const int buf = t & 1;

        if (t + 1 < NT) stageV(t + 1, buf ^ 1);

        // ---- phase B(t): HMMA from buf ----
        const unsigned se_h = sb + EOFF + buf * EBUF;
        const unsigned se_l = se_h + EVER;
        const unsigned sv_h = sb + VOFF + buf * VBUF;
        const unsigned sv_l = sv_h + VVER;
#pragma unroll
        for (int j = 0; j < 4; j++) {
            unsigned ebh[4][2], ebl[4][2];
#pragma unroll
            for (int nb = 0; nb < 4; nb++) {
                unsigned eoff = e_base + (unsigned)(nb * 8) * ROWB + (unsigned)(j * 32);
                ldm_x2(ebh[nb], se_h + eoff);
                ldm_x2(ebl[nb], se_l + eoff);
            }
#pragma unroll
            for (int i = 0; i < 2; i++) {
                unsigned vah[4], val[4];
                unsigned voff = v_base + (unsigned)(i * 16) * ROWB + (unsigned)(j * 32);
                ldm_x4(vah, sv_h + voff);
                ldm_x4(val, sv_l + voff);
#pragma unroll
                for (int nb = 0; nb < 4; nb++) {
                    mma16816(d[i][nb], vah, ebh[nb]);   // eh*vh
                    mma16816(d[i][nb], vah, ebl[nb]);   // el*vh
                    mma16816(d[i][nb], val, ebh[nb]);   // eh*vl
                }
            }
        }

        if (t + 1 < NT) phaseA(t + 1, buf ^ 1);

        CP_WAIT0();
        __syncthreads();
    }

    denom_s[half * 128 + mA] = dsum;
    __syncthreads();

    const float g = *gamma_p;
    const int gg = lane >> 2, tt2 = lane & 3;
#pragma unroll
    for (int nb = 0; nb < 4; nb++) {
        int ml = wm * 32 + nb * 8 + 2 * tt2;
        int mg = m0 + ml;
        float inv0 = g / (denom_s[ml] + denom_s[128 + ml]);
        float inv1 = g / (denom_s[ml + 1] + denom_s[128 + ml + 1]);
#pragma unroll
        for (int i = 0; i < 2; i++) {
            int c0 = wc * 32 + i * 16 + gg;
            int base0 = ((b * C) + c0) * L + mg;
            float2 x0 = *(const float2*)&x[base0];
            float2 o0 = make_float2(d[i][nb][0] * inv0 + x0.x,
                                    d[i][nb][1] * inv1 + x0.y);
            *(float2*)&out[base0] = o0;
            int base1 = ((b * C) + c0 + 8) * L + mg;
            float2 x1 = *(const float2*)&x[base1];
            float2 o1 = make_float2(d[i][nb][2] * inv0 + x1.x,
                                    d[i][nb][3] * inv1 + x1.y);
            *(float2*)&out[base1] = o1;
        }
    }
}

extern "C" void kernel_launch(void* const* d_in, const int* in_sizes, int n_in,
                              void* d_out, int out_size) {
    const float* x     = (const float*)d_in[0];
    const float* Wq    = (const float*)d_in[1];
    const float* bq    = (const float*)d_in[2];
    const float* Wk    = (const float*)d_in[3];
    const float* bk    = (const float*)d_in[4];
    const float* Wv    = (const float*)d_in[5];
    const float* bv    = (const float*)d_in[6];
    const float* gamma = (const float*)d_in[7];
    float* out = (float*)d_out;

    cudaFuncSetAttribute(attn_kernel, cudaFuncAttributeMaxDynamicSharedMemorySize, SMEM_BYTES);

    dim3 g1(BATCH, L / 256);
    proj_kernel<<<g1, 256>>>(x, Wq, bq, Wk, bk, Wv, bv);

    dim3 g2(BATCH, L / MTILE);
    attn_kernel<<<g2, 256, SMEM_BYTES>>>(x, gamma, out);
}